// round 9
// baseline (speedup 1.0000x reference)
#include <cuda_runtime.h>
#include <math.h>

#define BB 256
#define IND 512
#define OUTD 512
#define ED 256
#define DELTA_C 0.1f
#define LN_EPS_C 1e-5f

typedef unsigned long long u64;

// Scratch (device globals — no allocation allowed)
__device__ float g_Wt[IND * OUTD];         // Wt[i][o] = W[o][i]
__device__ float g_AWt[ED * OUTD];         // AWt[e][o] = attn_w[o][e]
__device__ u64 g_PE2[ED * IND];            // PE2[e][i] = (PE[i][e], PE[i][e])
__device__ float g_scores[IND * OUTD];     // scores[i][o]
__device__ float4 g_WM[IND * (OUTD / 2)];  // (w_lo, w_hi, m_lo, m_hi)

// ---- packed f32x2 helpers (sm_100+; only add/mul/fma exist packed) ----
__device__ __forceinline__ u64 pack2(float lo, float hi) {
    u64 r; asm("mov.b64 %0, {%1,%2};" : "=l"(r) : "f"(lo), "f"(hi)); return r;
}
#define FMA2(d,a,b,c) asm("fma.rn.f32x2 %0,%1,%2,%3;" : "=l"(d) : "l"(a),"l"(b),"l"(c))
#define MUL2(d,a,b)   asm("mul.rn.f32x2 %0,%1,%2;"    : "=l"(d) : "l"(a),"l"(b))
#define UNPACK2(lo,hi,v) asm("mov.b64 {%0,%1}, %2;" : "=f"(lo),"=f"(hi) : "l"(v))

// ============================================================
// Kernel 1: transposes / relayouts (reverted to R7 config — measured 4.5us).
//   blocks [0,256):   W[o][i]  -> g_Wt[i][o]
//   blocks [256,384): AW[o][e] -> g_AWt[e][o]
//   blocks [384,512): PE[i][e] -> g_PE2[e][i] (duplicated u64)
// ============================================================
__global__ __launch_bounds__(128) void kernel_prep(
    const float* __restrict__ W, const float* __restrict__ AW,
    const float* __restrict__ PE) {
    __shared__ float tile[32][33];
    const int blk = blockIdx.x;
    const int tid = threadIdx.x;
    const int tx = tid & 31, ty = tid >> 5;

    if (blk < 256) {
        int c = (blk & 15) * 32 + tx;
        int r0 = (blk >> 4) * 32;
#pragma unroll
        for (int j = 0; j < 32; j += 4)
            tile[ty + j][tx] = W[(r0 + ty + j) * IND + c];
        __syncthreads();
        int c2 = (blk >> 4) * 32 + tx;
        int r2 = (blk & 15) * 32;
#pragma unroll
        for (int j = 0; j < 32; j += 4)
            g_Wt[(r2 + ty + j) * OUTD + c2] = tile[tx][ty + j];
    } else if (blk < 384) {
        int t = blk - 256;
        int o0 = (t & 15) * 32;
        int e0 = (t >> 4) * 32;
#pragma unroll
        for (int j = 0; j < 32; j += 4)
            tile[ty + j][tx] = AW[(o0 + ty + j) * ED + e0 + tx];
        __syncthreads();
#pragma unroll
        for (int j = 0; j < 32; j += 4)
            g_AWt[(e0 + ty + j) * OUTD + o0 + tx] = tile[tx][ty + j];
    } else {
        int t = blk - 384;
        int i0 = (t & 15) * 32;
        int e0 = (t >> 4) * 32;
#pragma unroll
        for (int j = 0; j < 32; j += 4)
            tile[ty + j][tx] = PE[(i0 + ty + j) * ED + e0 + tx];
        __syncthreads();
#pragma unroll
        for (int j = 0; j < 32; j += 4) {
            float v = tile[tx][ty + j];
            g_PE2[(e0 + ty + j) * IND + i0 + tx] = pack2(v, v);
        }
    }
}

// ============================================================
// Kernel 2: tiled scores GEMM (unchanged — measured fine)
// ============================================================
__global__ __launch_bounds__(128) void kernel_scores(
    const float* __restrict__ AB) {
    __shared__ float awb[2][32][68];
    __shared__ u64 peb[2][32][34];

    const int tid = threadIdx.x;
    const int to = tid & 15;
    const int ti = tid >> 4;
    const int o0 = (blockIdx.x & 7) * 64;
    const int i0 = (blockIdx.x >> 3) * 32;

    const int sr = tid >> 4;
    const int sc = tid & 15;

    u64 acc[4][2];
    const u64 z = pack2(0.f, 0.f);
#pragma unroll
    for (int ii = 0; ii < 4; ii++) { acc[ii][0] = z; acc[ii][1] = z; }

    float4 qa[4];
    ulonglong2 qp[4];

    auto LDGC = [&](int e0) {
#pragma unroll
        for (int k = 0; k < 4; k++) {
            int row = sr + k * 8;
            qa[k] = *(const float4*)(g_AWt + (e0 + row) * OUTD + o0 + sc * 4);
            qp[k] = *(const ulonglong2*)(g_PE2 + (e0 + row) * IND + i0 + sc * 2);
        }
    };
    auto STSC = [&](int buf) {
#pragma unroll
        for (int k = 0; k < 4; k++) {
            int row = sr + k * 8;
            *(float4*)&awb[buf][row][sc * 4] = qa[k];
            *(ulonglong2*)&peb[buf][row][sc * 2] = qp[k];
        }
    };
    auto COMPUTE = [&](int buf) {
#pragma unroll 4
        for (int e = 0; e < 32; e++) {
            ulonglong2 a = *(const ulonglong2*)&awb[buf][e][4 * to];
            ulonglong2 p01 = *(const ulonglong2*)&peb[buf][e][4 * ti];
            ulonglong2 p23 = *(const ulonglong2*)&peb[buf][e][4 * ti + 2];
            FMA2(acc[0][0], p01.x, a.x, acc[0][0]);
            FMA2(acc[0][1], p01.x, a.y, acc[0][1]);
            FMA2(acc[1][0], p01.y, a.x, acc[1][0]);
            FMA2(acc[1][1], p01.y, a.y, acc[1][1]);
            FMA2(acc[2][0], p23.x, a.x, acc[2][0]);
            FMA2(acc[2][1], p23.x, a.y, acc[2][1]);
            FMA2(acc[3][0], p23.y, a.x, acc[3][0]);
            FMA2(acc[3][1], p23.y, a.y, acc[3][1]);
        }
    };

    LDGC(0);
    STSC(0);
    __syncthreads();
#pragma unroll 1
    for (int c = 0; c < 8; c++) {
        if (c < 7) LDGC(32 * (c + 1));
        COMPUTE(c & 1);
        if (c < 7) {
            STSC((c + 1) & 1);
            __syncthreads();
        }
    }

    float4 bb = *(const float4*)(AB + o0 + 4 * to);
#pragma unroll
    for (int ii = 0; ii < 4; ii++) {
        float f0, f1, f2, f3;
        UNPACK2(f0, f1, acc[ii][0]);
        UNPACK2(f2, f3, acc[ii][1]);
        float4 o4;
        o4.x = f0 + bb.x; o4.y = f1 + bb.y;
        o4.z = f2 + bb.z; o4.w = f3 + bb.w;
        *(float4*)(g_scores + (i0 + 4 * ti + ii) * OUTD + o0 + 4 * to) = o4;
    }
}

// ============================================================
// Kernel 3: LayerNorm -> sigmoid -> write interleaved g_WM float4
// ============================================================
__global__ __launch_bounds__(128) void kernel_lnwm(
    const float* __restrict__ LG, const float* __restrict__ LB) {
    const int tid = threadIdx.x;
    const int i0 = blockIdx.x * 4;
    const int w = tid >> 5, lane = tid & 31;
    __shared__ float mus[4], rss[4];

    {
        const float* row = g_scores + (i0 + w) * OUTD;
        float s = 0.f, s2 = 0.f;
#pragma unroll
        for (int k = 0; k < 16; k++) {
            float v = row[lane + 32 * k];
            s += v; s2 += v * v;
        }
#pragma unroll
        for (int off = 16; off > 0; off >>= 1) {
            s  += __shfl_xor_sync(0xffffffffu, s,  off);
            s2 += __shfl_xor_sync(0xffffffffu, s2, off);
        }
        if (lane == 0) {
            float mu = s * (1.f / OUTD);
            float var = s2 * (1.f / OUTD) - mu * mu;
            mus[w] = mu;
            rss[w] = rsqrtf(var + LN_EPS_C);
        }
    }
    __syncthreads();
#pragma unroll
    for (int ii = 0; ii < 4; ii++) {
        float mu = mus[ii], rs = rss[ii];
        const int i = i0 + ii;
#pragma unroll
        for (int j = 0; j < 2; j++) {
            int p = tid + j * 128;
            float2 s2v = *(const float2*)(g_scores + i * OUTD + 2 * p);
            float2 w2v = *(const float2*)(g_Wt + i * OUTD + 2 * p);
            float glo = LG[2 * p],     blo = LB[2 * p];
            float ghi = LG[2 * p + 1], bhi = LB[2 * p + 1];
            float vlo = (s2v.x - mu) * rs * glo + blo;
            float vhi = (s2v.y - mu) * rs * ghi + bhi;
            float siglo = 1.f / (1.f + __expf(-vlo));
            float sighi = 1.f / (1.f + __expf(-vhi));
            float4 q;
            q.x = w2v.x; q.y = w2v.y;
            q.z = fabsf(w2v.x) * siglo;
            q.w = fabsf(w2v.y) * sighi;
            g_WM[i * (OUTD / 2) + p] = q;
        }
    }
}

// ============================================================
// Kernel 4 (main): out[b,o] = x@Wt + 0.1*(max_i t*M - sum_i t*M)
//
// grid (16 o-tiles of 16 pairs, 32 b-tiles of 8) = 512 blocks, 256 thr,
// 3 blocks/SM (85-reg cap), 64KB dynamic smem (xt for 8 batches).
// Thread: to = tid&15 (its o-pair for ALL 8 batches), hs = tid>>4
// -> i-chunk of 32. One LDG.128 per i per thread amortized over
// 16 output elements. Pointer-walk addressing (imm offsets, no IMAD
// chains). 4-deep ping-pong prefetch (MLP 4). Cross-hs smem reduction.
// ============================================================
#define MAIN_SMEM (8 * IND * 16)  // 64 KB

__global__ __launch_bounds__(256, 3) void kernel_main(
    const float* __restrict__ X, float* __restrict__ out) {
    extern __shared__ char smem_raw[];
    ulonglong2 (*xt)[IND] = (ulonglong2 (*)[IND])smem_raw;  // [8][512]
    float* red = (float*)smem_raw;

    const int tid = threadIdx.x;
    const int to = tid & 15;
    const int hs = tid >> 4;        // [0,16), i-chunk of 32
    const int b0 = blockIdx.y * 8;
    const int ib = hs * 32;

    // Stage x and t = x*|x| duplicated for f32x2 broadcast (8 batches).
#pragma unroll
    for (int r = 0; r < 4; r++) {
        int idx = tid + r * 256;          // [0, 1024): b = idx>>7, i4 = idx&127
        int b = idx >> 7, i4 = idx & 127;
        float4 xv = *(const float4*)(X + (b0 + b) * IND + i4 * 4);
        float xs[4] = {xv.x, xv.y, xv.z, xv.w};
#pragma unroll
        for (int k = 0; k < 4; k++) {
            float x1 = xs[k];
            float t1 = x1 * fabsf(x1);
            xt[b][i4 * 4 + k] = make_ulonglong2(pack2(x1, x1), pack2(t1, t1));
        }
    }
    __syncthreads();

    u64 c[8];
    float mxl[8], mxh[8];
    const u64 z = pack2(0.f, 0.f);
    const u64 n01 = pack2(-DELTA_C, -DELTA_C);
#pragma unroll
    for (int b = 0; b < 8; b++) {
        c[b] = z;
        mxl[b] = -INFINITY; mxh[b] = -INFINITY;
    }

    // wm pointer for this thread's o-pair; row stride 256 ulonglong2.
    const ulonglong2* __restrict__ wp =
        (const ulonglong2*)g_WM + (u64)ib * 256 + blockIdx.x * 16 + to;

    ulonglong2 qA[4], qB[4];

    auto LOAD4 = [&](ulonglong2 q[4], const ulonglong2* p) {
        q[0] = p[0];
        q[1] = p[256];
        q[2] = p[512];
        q[3] = p[768];
    };
    auto COMP4 = [&](const ulonglong2 q[4], int i0g) {
#pragma unroll
        for (int k = 0; k < 4; k++) {
#pragma unroll
            for (int b = 0; b < 8; b++) {
                ulonglong2 v = xt[b][i0g + k];
                FMA2(c[b], v.x, q[k].x, c[b]);
                u64 p; MUL2(p, v.y, q[k].y);
                FMA2(c[b], p, n01, c[b]);
                float plo, phi; UNPACK2(plo, phi, p);
                mxl[b] = fmaxf(mxl[b], plo);
                mxh[b] = fmaxf(mxh[b], phi);
            }
        }
    };

    LOAD4(qA, wp);                    // group 0
    wp += 1024;
#pragma unroll 1
    for (int gg = 0; gg < 4; gg++) {
        const int i0g = ib + gg * 8;
        LOAD4(qB, wp);                // group 2gg+1
        wp += 1024;
        COMP4(qA, i0g);
        if (gg < 3) {
            LOAD4(qA, wp);            // group 2gg+2
            wp += 1024;
        }
        COMP4(qB, i0g + 4);
    }

    __syncthreads();  // xt done; reuse as reduction buffer

    // red planes: kind k in {c_lo, c_hi, mx_lo, mx_hi} x [b][hs][to]
#define RIDX(k, b, s, t) ((((k) * 8 + (b)) * 16 + (s)) * 16 + (t))
#pragma unroll
    for (int b = 0; b < 8; b++) {
        float clo, chi;
        UNPACK2(clo, chi, c[b]);
        red[RIDX(0, b, hs, to)] = clo;
        red[RIDX(1, b, hs, to)] = chi;
        red[RIDX(2, b, hs, to)] = mxl[b];
        red[RIDX(3, b, hs, to)] = mxh[b];
    }
    __syncthreads();

    // Final combine: 256 threads, thread -> (b2 = tid>>5, o = tid&31).
    {
        const int b2 = tid >> 5;
        const int o = tid & 31;
        const int pr = o >> 1;       // pair index
        const int h = o & 1;         // lo/hi half
        float s = 0.f, M = -INFINITY;
#pragma unroll
        for (int g = 0; g < 16; g++) {
            s += red[RIDX(h, b2, g, pr)];
            M = fmaxf(M, red[RIDX(2 + h, b2, g, pr)]);
        }
        out[(b0 + b2) * OUTD + blockIdx.x * 32 + o] = s + DELTA_C * M;
    }
#undef RIDX
}

// ============================================================
extern "C" void kernel_launch(void* const* d_in, const int* in_sizes, int n_in,
                              void* d_out, int out_size) {
    const float* x  = (const float*)d_in[0];
    const float* w  = (const float*)d_in[1];
    const float* pe = (const float*)d_in[2];
    const float* aw = (const float*)d_in[3];
    const float* ab = (const float*)d_in[4];
    const float* lg = (const float*)d_in[5];
    const float* lb = (const float*)d_in[6];
    float* out = (float*)d_out;

    cudaFuncSetAttribute(kernel_main,
                         cudaFuncAttributeMaxDynamicSharedMemorySize,
                         MAIN_SMEM);

    kernel_prep<<<512, 128>>>(w, aw, pe);
    kernel_scores<<<128, 128>>>(ab);
    kernel_lnwm<<<128, 128>>>(lg, lb);
    kernel_main<<<dim3(16, 32), 256, MAIN_SMEM>>>(x, out);
}

// round 10
// speedup vs baseline: 1.0234x; 1.0234x over previous
#include <cuda_runtime.h>
#include <math.h>

#define BB 256
#define IND 512
#define OUTD 512
#define ED 256
#define DELTA_C 0.1f
#define LN_EPS_C 1e-5f

typedef unsigned long long u64;

// Scratch (device globals — no allocation allowed)
__device__ float g_Wt[IND * OUTD];         // Wt[i][o] = W[o][i]
__device__ float g_AWt[ED * OUTD];         // AWt[e][o] = attn_w[o][e]
__device__ u64 g_PE2[ED * IND];            // PE2[e][i] = (PE[i][e], PE[i][e])
__device__ float g_scores[IND * OUTD];     // scores[i][o]
__device__ float4 g_WM[IND * (OUTD / 2)];  // (w_lo, w_hi, m_lo, m_hi)

// ---- packed f32x2 helpers (sm_100+; only add/mul/fma exist packed) ----
__device__ __forceinline__ u64 pack2(float lo, float hi) {
    u64 r; asm("mov.b64 %0, {%1,%2};" : "=l"(r) : "f"(lo), "f"(hi)); return r;
}
#define FMA2(d,a,b,c) asm("fma.rn.f32x2 %0,%1,%2,%3;" : "=l"(d) : "l"(a),"l"(b),"l"(c))
#define MUL2(d,a,b)   asm("mul.rn.f32x2 %0,%1,%2;"    : "=l"(d) : "l"(a),"l"(b))
#define UNPACK2(lo,hi,v) asm("mov.b64 {%0,%1}, %2;" : "=f"(lo),"=f"(hi) : "l"(v))

// ============================================================
// Kernel 1: transposes / relayouts (unchanged — measured 4.5us).
// ============================================================
__global__ __launch_bounds__(128) void kernel_prep(
    const float* __restrict__ W, const float* __restrict__ AW,
    const float* __restrict__ PE) {
    __shared__ float tile[32][33];
    const int blk = blockIdx.x;
    const int tid = threadIdx.x;
    const int tx = tid & 31, ty = tid >> 5;

    if (blk < 256) {
        int c = (blk & 15) * 32 + tx;
        int r0 = (blk >> 4) * 32;
#pragma unroll
        for (int j = 0; j < 32; j += 4)
            tile[ty + j][tx] = W[(r0 + ty + j) * IND + c];
        __syncthreads();
        int c2 = (blk >> 4) * 32 + tx;
        int r2 = (blk & 15) * 32;
#pragma unroll
        for (int j = 0; j < 32; j += 4)
            g_Wt[(r2 + ty + j) * OUTD + c2] = tile[tx][ty + j];
    } else if (blk < 384) {
        int t = blk - 256;
        int o0 = (t & 15) * 32;
        int e0 = (t >> 4) * 32;
#pragma unroll
        for (int j = 0; j < 32; j += 4)
            tile[ty + j][tx] = AW[(o0 + ty + j) * ED + e0 + tx];
        __syncthreads();
#pragma unroll
        for (int j = 0; j < 32; j += 4)
            g_AWt[(e0 + ty + j) * OUTD + o0 + tx] = tile[tx][ty + j];
    } else {
        int t = blk - 384;
        int i0 = (t & 15) * 32;
        int e0 = (t >> 4) * 32;
#pragma unroll
        for (int j = 0; j < 32; j += 4)
            tile[ty + j][tx] = PE[(i0 + ty + j) * ED + e0 + tx];
        __syncthreads();
#pragma unroll
        for (int j = 0; j < 32; j += 4) {
            float v = tile[tx][ty + j];
            g_PE2[(e0 + ty + j) * IND + i0 + tx] = pack2(v, v);
        }
    }
}

// ============================================================
// Kernel 2: tiled scores GEMM (unchanged — measured fine)
// ============================================================
__global__ __launch_bounds__(128) void kernel_scores(
    const float* __restrict__ AB) {
    __shared__ float awb[2][32][68];
    __shared__ u64 peb[2][32][34];

    const int tid = threadIdx.x;
    const int to = tid & 15;
    const int ti = tid >> 4;
    const int o0 = (blockIdx.x & 7) * 64;
    const int i0 = (blockIdx.x >> 3) * 32;

    const int sr = tid >> 4;
    const int sc = tid & 15;

    u64 acc[4][2];
    const u64 z = pack2(0.f, 0.f);
#pragma unroll
    for (int ii = 0; ii < 4; ii++) { acc[ii][0] = z; acc[ii][1] = z; }

    float4 qa[4];
    ulonglong2 qp[4];

    auto LDGC = [&](int e0) {
#pragma unroll
        for (int k = 0; k < 4; k++) {
            int row = sr + k * 8;
            qa[k] = *(const float4*)(g_AWt + (e0 + row) * OUTD + o0 + sc * 4);
            qp[k] = *(const ulonglong2*)(g_PE2 + (e0 + row) * IND + i0 + sc * 2);
        }
    };
    auto STSC = [&](int buf) {
#pragma unroll
        for (int k = 0; k < 4; k++) {
            int row = sr + k * 8;
            *(float4*)&awb[buf][row][sc * 4] = qa[k];
            *(ulonglong2*)&peb[buf][row][sc * 2] = qp[k];
        }
    };
    auto COMPUTE = [&](int buf) {
#pragma unroll 4
        for (int e = 0; e < 32; e++) {
            ulonglong2 a = *(const ulonglong2*)&awb[buf][e][4 * to];
            ulonglong2 p01 = *(const ulonglong2*)&peb[buf][e][4 * ti];
            ulonglong2 p23 = *(const ulonglong2*)&peb[buf][e][4 * ti + 2];
            FMA2(acc[0][0], p01.x, a.x, acc[0][0]);
            FMA2(acc[0][1], p01.x, a.y, acc[0][1]);
            FMA2(acc[1][0], p01.y, a.x, acc[1][0]);
            FMA2(acc[1][1], p01.y, a.y, acc[1][1]);
            FMA2(acc[2][0], p23.x, a.x, acc[2][0]);
            FMA2(acc[2][1], p23.x, a.y, acc[2][1]);
            FMA2(acc[3][0], p23.y, a.x, acc[3][0]);
            FMA2(acc[3][1], p23.y, a.y, acc[3][1]);
        }
    };

    LDGC(0);
    STSC(0);
    __syncthreads();
#pragma unroll 1
    for (int c = 0; c < 8; c++) {
        if (c < 7) LDGC(32 * (c + 1));
        COMPUTE(c & 1);
        if (c < 7) {
            STSC((c + 1) & 1);
            __syncthreads();
        }
    }

    float4 bb = *(const float4*)(AB + o0 + 4 * to);
#pragma unroll
    for (int ii = 0; ii < 4; ii++) {
        float f0, f1, f2, f3;
        UNPACK2(f0, f1, acc[ii][0]);
        UNPACK2(f2, f3, acc[ii][1]);
        float4 o4;
        o4.x = f0 + bb.x; o4.y = f1 + bb.y;
        o4.z = f2 + bb.z; o4.w = f3 + bb.w;
        *(float4*)(g_scores + (i0 + 4 * ti + ii) * OUTD + o0 + 4 * to) = o4;
    }
}

// ============================================================
// Kernel 3: LayerNorm -> sigmoid -> write interleaved g_WM float4
// ============================================================
__global__ __launch_bounds__(128) void kernel_lnwm(
    const float* __restrict__ LG, const float* __restrict__ LB) {
    const int tid = threadIdx.x;
    const int i0 = blockIdx.x * 4;
    const int w = tid >> 5, lane = tid & 31;
    __shared__ float mus[4], rss[4];

    {
        const float* row = g_scores + (i0 + w) * OUTD;
        float s = 0.f, s2 = 0.f;
#pragma unroll
        for (int k = 0; k < 16; k++) {
            float v = row[lane + 32 * k];
            s += v; s2 += v * v;
        }
#pragma unroll
        for (int off = 16; off > 0; off >>= 1) {
            s  += __shfl_xor_sync(0xffffffffu, s,  off);
            s2 += __shfl_xor_sync(0xffffffffu, s2, off);
        }
        if (lane == 0) {
            float mu = s * (1.f / OUTD);
            float var = s2 * (1.f / OUTD) - mu * mu;
            mus[w] = mu;
            rss[w] = rsqrtf(var + LN_EPS_C);
        }
    }
    __syncthreads();
#pragma unroll
    for (int ii = 0; ii < 4; ii++) {
        float mu = mus[ii], rs = rss[ii];
        const int i = i0 + ii;
#pragma unroll
        for (int j = 0; j < 2; j++) {
            int p = tid + j * 128;
            float2 s2v = *(const float2*)(g_scores + i * OUTD + 2 * p);
            float2 w2v = *(const float2*)(g_Wt + i * OUTD + 2 * p);
            float glo = LG[2 * p],     blo = LB[2 * p];
            float ghi = LG[2 * p + 1], bhi = LB[2 * p + 1];
            float vlo = (s2v.x - mu) * rs * glo + blo;
            float vhi = (s2v.y - mu) * rs * ghi + bhi;
            float siglo = 1.f / (1.f + __expf(-vlo));
            float sighi = 1.f / (1.f + __expf(-vhi));
            float4 q;
            q.x = w2v.x; q.y = w2v.y;
            q.z = fabsf(w2v.x) * siglo;
            q.w = fabsf(w2v.y) * sighi;
            g_WM[i * (OUTD / 2) + p] = q;
        }
    }
}

// ============================================================
// Kernel 4 (main): out[b,o] = x@Wt + 0.1*(max_i t*M - sum_i t*M)
//
// Same shape as R9 (grid (16,32), 256 thr, 3/SM, 64KB smem), but the
// hot loop is POINTER-WALKED: one byte pointer per operand stream,
// advanced by a constant per 8-i group; all per-b / per-k offsets are
// compile-time immediates -> LDS/LDG [R+imm], no per-access IMAD.
// ============================================================
#define MAIN_SMEM (8 * IND * 16)  // 64 KB

// byte strides
#define XT_B_STRIDE 8192          // 512 i * 16 B
#define WM_ROW_BYTES 4096         // 256 pairs * 16 B

__global__ __launch_bounds__(256, 3) void kernel_main(
    const float* __restrict__ X, float* __restrict__ out) {
    extern __shared__ char smem_raw[];
    ulonglong2 (*xt)[IND] = (ulonglong2 (*)[IND])smem_raw;  // [8][512]
    float* red = (float*)smem_raw;

    const int tid = threadIdx.x;
    const int to = tid & 15;
    const int hs = tid >> 4;        // [0,16), i-chunk of 32
    const int b0 = blockIdx.y * 8;
    const int ib = hs * 32;

    // Stage x and t = x*|x| duplicated for f32x2 broadcast (8 batches).
#pragma unroll
    for (int r = 0; r < 4; r++) {
        int idx = tid + r * 256;
        int b = idx >> 7, i4 = idx & 127;
        float4 xv = *(const float4*)(X + (b0 + b) * IND + i4 * 4);
        float xs[4] = {xv.x, xv.y, xv.z, xv.w};
#pragma unroll
        for (int k = 0; k < 4; k++) {
            float x1 = xs[k];
            float t1 = x1 * fabsf(x1);
            xt[b][i4 * 4 + k] = make_ulonglong2(pack2(x1, x1), pack2(t1, t1));
        }
    }
    __syncthreads();

    u64 c[8];
    float mxl[8], mxh[8];
    const u64 z = pack2(0.f, 0.f);
    const u64 n01 = pack2(-DELTA_C, -DELTA_C);
#pragma unroll
    for (int b = 0; b < 8; b++) {
        c[b] = z;
        mxl[b] = -INFINITY; mxh[b] = -INFINITY;
    }

    // walking pointers (all inner offsets are immediates)
    const char* xp = smem_raw + ib * 16;                 // xt[0][ib]
    const char* wp = (const char*)g_WM +
                     ((u64)ib * 256 + blockIdx.x * 16 + to) * 16;

    ulonglong2 qA[4], qB[4];

#define LOADW(q, base) do {                                         \
        (q)[0] = *(const ulonglong2*)((base));                       \
        (q)[1] = *(const ulonglong2*)((base) + 1 * WM_ROW_BYTES);    \
        (q)[2] = *(const ulonglong2*)((base) + 2 * WM_ROW_BYTES);    \
        (q)[3] = *(const ulonglong2*)((base) + 3 * WM_ROW_BYTES);    \
    } while (0)

#define COMP4(q, xbase) do {                                         \
        _Pragma("unroll")                                            \
        for (int k = 0; k < 4; k++) {                                \
            _Pragma("unroll")                                        \
            for (int b = 0; b < 8; b++) {                            \
                ulonglong2 v = *(const ulonglong2*)(                 \
                    (xbase) + b * XT_B_STRIDE + k * 16);             \
                FMA2(c[b], v.x, (q)[k].x, c[b]);                     \
                u64 p; MUL2(p, v.y, (q)[k].y);                       \
                FMA2(c[b], p, n01, c[b]);                            \
                float plo, phi; UNPACK2(plo, phi, p);                \
                mxl[b] = fmaxf(mxl[b], plo);                         \
                mxh[b] = fmaxf(mxh[b], phi);                         \
            }                                                        \
        }                                                            \
    } while (0)

    LOADW(qA, wp);
#pragma unroll 1
    for (int gg = 0; gg < 4; gg++) {
        LOADW(qB, wp + 4 * WM_ROW_BYTES);
        COMP4(qA, xp);
        if (gg < 3) LOADW(qA, wp + 8 * WM_ROW_BYTES);
        COMP4(qB, xp + 64);
        wp += 8 * WM_ROW_BYTES;
        xp += 128;
    }
#undef LOADW
#undef COMP4

    __syncthreads();  // xt done; reuse as reduction buffer

    // red planes: kind k in {c_lo, c_hi, mx_lo, mx_hi} x [b][hs][to]
#define RIDX(k, b, s, t) ((((k) * 8 + (b)) * 16 + (s)) * 16 + (t))
#pragma unroll
    for (int b = 0; b < 8; b++) {
        float clo, chi;
        UNPACK2(clo, chi, c[b]);
        red[RIDX(0, b, hs, to)] = clo;
        red[RIDX(1, b, hs, to)] = chi;
        red[RIDX(2, b, hs, to)] = mxl[b];
        red[RIDX(3, b, hs, to)] = mxh[b];
    }
    __syncthreads();

    // Final combine: 256 threads, thread -> (b2 = tid>>5, o = tid&31).
    {
        const int b2 = tid >> 5;
        const int o = tid & 31;
        const int pr = o >> 1;       // pair index
        const int h = o & 1;         // lo/hi half
        float s = 0.f, M = -INFINITY;
#pragma unroll
        for (int g = 0; g < 16; g++) {
            s += red[RIDX(h, b2, g, pr)];
            M = fmaxf(M, red[RIDX(2 + h, b2, g, pr)]);
        }
        out[(b0 + b2) * OUTD + blockIdx.x * 32 + o] = s + DELTA_C * M;
    }
#undef RIDX
}

// ============================================================
extern "C" void kernel_launch(void* const* d_in, const int* in_sizes, int n_in,
                              void* d_out, int out_size) {
    const float* x  = (const float*)d_in[0];
    const float* w  = (const float*)d_in[1];
    const float* pe = (const float*)d_in[2];
    const float* aw = (const float*)d_in[3];
    const float* ab = (const float*)d_in[4];
    const float* lg = (const float*)d_in[5];
    const float* lb = (const float*)d_in[6];
    float* out = (float*)d_out;

    cudaFuncSetAttribute(kernel_main,
                         cudaFuncAttributeMaxDynamicSharedMemorySize,
                         MAIN_SMEM);

    kernel_prep<<<512, 128>>>(w, aw, pe);
    kernel_scores<<<128, 128>>>(ab);
    kernel_lnwm<<<128, 128>>>(lg, lb);
    kernel_main<<<dim3(16, 32), 256, MAIN_SMEM>>>(x, out);
}

// round 11
// speedup vs baseline: 1.0302x; 1.0066x over previous
#include <cuda_runtime.h>
#include <math.h>

#define BB 256
#define IND 512
#define OUTD 512
#define ED 256
#define DELTA_C 0.1f
#define LN_EPS_C 1e-5f

typedef unsigned long long u64;

// Scratch (device globals — no allocation allowed)
__device__ float g_Wt[IND * OUTD];         // Wt[i][o] = W[o][i]
__device__ float g_AWt[ED * OUTD];         // AWt[e][o] = attn_w[o][e]
__device__ u64 g_PE2[ED * IND];            // PE2[e][i] = (PE[i][e], PE[i][e])
__device__ float g_scores[IND * OUTD];     // scores[i][o]
__device__ float4 g_WM[IND * (OUTD / 2)];  // (w_lo, w_hi, m_lo, m_hi)

// ---- packed f32x2 helpers (sm_100+; only add/mul/fma exist packed) ----
__device__ __forceinline__ u64 pack2(float lo, float hi) {
    u64 r; asm("mov.b64 %0, {%1,%2};" : "=l"(r) : "f"(lo), "f"(hi)); return r;
}
#define FMA2(d,a,b,c) asm("fma.rn.f32x2 %0,%1,%2,%3;" : "=l"(d) : "l"(a),"l"(b),"l"(c))
#define MUL2(d,a,b)   asm("mul.rn.f32x2 %0,%1,%2;"    : "=l"(d) : "l"(a),"l"(b))
#define UNPACK2(lo,hi,v) asm("mov.b64 {%0,%1}, %2;" : "=f"(lo),"=f"(hi) : "l"(v))

// ============================================================
// Kernel 1: transposes / relayouts (unchanged)
// ============================================================
__global__ __launch_bounds__(128) void kernel_prep(
    const float* __restrict__ W, const float* __restrict__ AW,
    const float* __restrict__ PE) {
    __shared__ float tile[32][33];
    const int blk = blockIdx.x;
    const int tid = threadIdx.x;
    const int tx = tid & 31, ty = tid >> 5;

    if (blk < 256) {
        int c = (blk & 15) * 32 + tx;
        int r0 = (blk >> 4) * 32;
#pragma unroll
        for (int j = 0; j < 32; j += 4)
            tile[ty + j][tx] = W[(r0 + ty + j) * IND + c];
        __syncthreads();
        int c2 = (blk >> 4) * 32 + tx;
        int r2 = (blk & 15) * 32;
#pragma unroll
        for (int j = 0; j < 32; j += 4)
            g_Wt[(r2 + ty + j) * OUTD + c2] = tile[tx][ty + j];
    } else if (blk < 384) {
        int t = blk - 256;
        int o0 = (t & 15) * 32;
        int e0 = (t >> 4) * 32;
#pragma unroll
        for (int j = 0; j < 32; j += 4)
            tile[ty + j][tx] = AW[(o0 + ty + j) * ED + e0 + tx];
        __syncthreads();
#pragma unroll
        for (int j = 0; j < 32; j += 4)
            g_AWt[(e0 + ty + j) * OUTD + o0 + tx] = tile[tx][ty + j];
    } else {
        int t = blk - 384;
        int i0 = (t & 15) * 32;
        int e0 = (t >> 4) * 32;
#pragma unroll
        for (int j = 0; j < 32; j += 4)
            tile[ty + j][tx] = PE[(i0 + ty + j) * ED + e0 + tx];
        __syncthreads();
#pragma unroll
        for (int j = 0; j < 32; j += 4) {
            float v = tile[tx][ty + j];
            g_PE2[(e0 + ty + j) * IND + i0 + tx] = pack2(v, v);
        }
    }
}

// ============================================================
// Kernel 2: tiled scores GEMM (unchanged)
// ============================================================
__global__ __launch_bounds__(128) void kernel_scores(
    const float* __restrict__ AB) {
    __shared__ float awb[2][32][68];
    __shared__ u64 peb[2][32][34];

    const int tid = threadIdx.x;
    const int to = tid & 15;
    const int ti = tid >> 4;
    const int o0 = (blockIdx.x & 7) * 64;
    const int i0 = (blockIdx.x >> 3) * 32;

    const int sr = tid >> 4;
    const int sc = tid & 15;

    u64 acc[4][2];
    const u64 z = pack2(0.f, 0.f);
#pragma unroll
    for (int ii = 0; ii < 4; ii++) { acc[ii][0] = z; acc[ii][1] = z; }

    float4 qa[4];
    ulonglong2 qp[4];

    auto LDGC = [&](int e0) {
#pragma unroll
        for (int k = 0; k < 4; k++) {
            int row = sr + k * 8;
            qa[k] = *(const float4*)(g_AWt + (e0 + row) * OUTD + o0 + sc * 4);
            qp[k] = *(const ulonglong2*)(g_PE2 + (e0 + row) * IND + i0 + sc * 2);
        }
    };
    auto STSC = [&](int buf) {
#pragma unroll
        for (int k = 0; k < 4; k++) {
            int row = sr + k * 8;
            *(float4*)&awb[buf][row][sc * 4] = qa[k];
            *(ulonglong2*)&peb[buf][row][sc * 2] = qp[k];
        }
    };
    auto COMPUTE = [&](int buf) {
#pragma unroll 4
        for (int e = 0; e < 32; e++) {
            ulonglong2 a = *(const ulonglong2*)&awb[buf][e][4 * to];
            ulonglong2 p01 = *(const ulonglong2*)&peb[buf][e][4 * ti];
            ulonglong2 p23 = *(const ulonglong2*)&peb[buf][e][4 * ti + 2];
            FMA2(acc[0][0], p01.x, a.x, acc[0][0]);
            FMA2(acc[0][1], p01.x, a.y, acc[0][1]);
            FMA2(acc[1][0], p01.y, a.x, acc[1][0]);
            FMA2(acc[1][1], p01.y, a.y, acc[1][1]);
            FMA2(acc[2][0], p23.x, a.x, acc[2][0]);
            FMA2(acc[2][1], p23.x, a.y, acc[2][1]);
            FMA2(acc[3][0], p23.y, a.x, acc[3][0]);
            FMA2(acc[3][1], p23.y, a.y, acc[3][1]);
        }
    };

    LDGC(0);
    STSC(0);
    __syncthreads();
#pragma unroll 1
    for (int c = 0; c < 8; c++) {
        if (c < 7) LDGC(32 * (c + 1));
        COMPUTE(c & 1);
        if (c < 7) {
            STSC((c + 1) & 1);
            __syncthreads();
        }
    }

    float4 bb = *(const float4*)(AB + o0 + 4 * to);
#pragma unroll
    for (int ii = 0; ii < 4; ii++) {
        float f0, f1, f2, f3;
        UNPACK2(f0, f1, acc[ii][0]);
        UNPACK2(f2, f3, acc[ii][1]);
        float4 o4;
        o4.x = f0 + bb.x; o4.y = f1 + bb.y;
        o4.z = f2 + bb.z; o4.w = f3 + bb.w;
        *(float4*)(g_scores + (i0 + 4 * ti + ii) * OUTD + o0 + 4 * to) = o4;
    }
}

// ============================================================
// Kernel 3: LayerNorm -> sigmoid -> write interleaved g_WM float4
// ============================================================
__global__ __launch_bounds__(128) void kernel_lnwm(
    const float* __restrict__ LG, const float* __restrict__ LB) {
    const int tid = threadIdx.x;
    const int i0 = blockIdx.x * 4;
    const int w = tid >> 5, lane = tid & 31;
    __shared__ float mus[4], rss[4];

    {
        const float* row = g_scores + (i0 + w) * OUTD;
        float s = 0.f, s2 = 0.f;
#pragma unroll
        for (int k = 0; k < 16; k++) {
            float v = row[lane + 32 * k];
            s += v; s2 += v * v;
        }
#pragma unroll
        for (int off = 16; off > 0; off >>= 1) {
            s  += __shfl_xor_sync(0xffffffffu, s,  off);
            s2 += __shfl_xor_sync(0xffffffffu, s2, off);
        }
        if (lane == 0) {
            float mu = s * (1.f / OUTD);
            float var = s2 * (1.f / OUTD) - mu * mu;
            mus[w] = mu;
            rss[w] = rsqrtf(var + LN_EPS_C);
        }
    }
    __syncthreads();
#pragma unroll
    for (int ii = 0; ii < 4; ii++) {
        float mu = mus[ii], rs = rss[ii];
        const int i = i0 + ii;
#pragma unroll
        for (int j = 0; j < 2; j++) {
            int p = tid + j * 128;
            float2 s2v = *(const float2*)(g_scores + i * OUTD + 2 * p);
            float2 w2v = *(const float2*)(g_Wt + i * OUTD + 2 * p);
            float glo = LG[2 * p],     blo = LB[2 * p];
            float ghi = LG[2 * p + 1], bhi = LB[2 * p + 1];
            float vlo = (s2v.x - mu) * rs * glo + blo;
            float vhi = (s2v.y - mu) * rs * ghi + bhi;
            float siglo = 1.f / (1.f + __expf(-vlo));
            float sighi = 1.f / (1.f + __expf(-vhi));
            float4 q;
            q.x = w2v.x; q.y = w2v.y;
            q.z = fabsf(w2v.x) * siglo;
            q.w = fabsf(w2v.y) * sighi;
            g_WM[i * (OUTD / 2) + p] = q;
        }
    }
}

// ============================================================
// Kernel 4 (main): out[b,o] = x@Wt + 0.1*(max_i t*M - sum_i t*M)
//
// grid (8 o-tiles of 64, 64 b-tiles of 4) = 512 blocks, 256 thr,
// 4 blocks/SM, 32KB STATIC smem -> entire grid in ONE wave (592 slots).
// Thread: to=tid&15 -> o-pairs {bx*32+to, +16}; hs=tid>>4 -> 32-i chunk.
// 4 batches x 2 o-pairs per thread: each LDS.128 feeds 4 outputs
// (halves crossbar load vs b=8 layout). Pointer-walk immediates.
// 1-i ping-pong LDG prefetch. Cross-hs smem reduction (reuses xt).
// ============================================================
#define XT_B_BYTES 8192           // 512 i * 16 B
#define WM_ROW_BYTES 4096         // 256 pairs * 16 B

__global__ __launch_bounds__(256, 4) void kernel_main(
    const float* __restrict__ X, float* __restrict__ out) {
    __shared__ ulonglong2 xt[4][IND];          // 32 KB
    float* red = (float*)xt;                   // reused after compute
    char* smem_raw = (char*)xt;

    const int tid = threadIdx.x;
    const int to = tid & 15;
    const int hs = tid >> 4;        // [0,16), i-chunk of 32
    const int b0 = blockIdx.y * 4;
    const int ib = hs * 32;

    // Stage x and t = x*|x| duplicated for f32x2 broadcast (4 batches).
#pragma unroll
    for (int r = 0; r < 2; r++) {
        int idx = tid + r * 256;          // [0,512): b = idx>>7, i4 = idx&127
        int b = idx >> 7, i4 = idx & 127;
        float4 xv = *(const float4*)(X + (b0 + b) * IND + i4 * 4);
        float xs[4] = {xv.x, xv.y, xv.z, xv.w};
#pragma unroll
        for (int k = 0; k < 4; k++) {
            float x1 = xs[k];
            float t1 = x1 * fabsf(x1);
            xt[b][i4 * 4 + k] = make_ulonglong2(pack2(x1, x1), pack2(t1, t1));
        }
    }
    __syncthreads();

    u64 c[4][2];
    float mxl[4][2], mxh[4][2];
    const u64 z = pack2(0.f, 0.f);
    const u64 n01 = pack2(-DELTA_C, -DELTA_C);
#pragma unroll
    for (int b = 0; b < 4; b++) {
        c[b][0] = z; c[b][1] = z;
        mxl[b][0] = -INFINITY; mxl[b][1] = -INFINITY;
        mxh[b][0] = -INFINITY; mxh[b][1] = -INFINITY;
    }

    // walking pointers (all inner offsets are immediates)
    const char* xp = smem_raw + ib * 16;                 // xt[0][ib]
    const char* wp = (const char*)g_WM +
                     ((u64)ib * 256 + blockIdx.x * 32 + to) * 16;
    // pair A at wp+0, pair B at wp+256 (16 pairs * 16B)

    ulonglong2 qa, qb, na, nb;

    // compute one i from (A-pair qa, B-pair qb) at xt byte base xb
#define COMP1(QA, QB, xb) do {                                       \
        _Pragma("unroll")                                            \
        for (int b = 0; b < 4; b++) {                                \
            ulonglong2 v = *(const ulonglong2*)((xb) + b * XT_B_BYTES); \
            FMA2(c[b][0], v.x, (QA).x, c[b][0]);                     \
            u64 pa; MUL2(pa, v.y, (QA).y);                           \
            FMA2(c[b][0], pa, n01, c[b][0]);                         \
            float palo, pahi; UNPACK2(palo, pahi, pa);               \
            mxl[b][0] = fmaxf(mxl[b][0], palo);                      \
            mxh[b][0] = fmaxf(mxh[b][0], pahi);                      \
            FMA2(c[b][1], v.x, (QB).x, c[b][1]);                     \
            u64 pb; MUL2(pb, v.y, (QB).y);                           \
            FMA2(c[b][1], pb, n01, c[b][1]);                         \
            float pblo, pbhi; UNPACK2(pblo, pbhi, pb);               \
            mxl[b][1] = fmaxf(mxl[b][1], pblo);                      \
            mxh[b][1] = fmaxf(mxh[b][1], pbhi);                      \
        }                                                            \
    } while (0)

    qa = *(const ulonglong2*)(wp);
    qb = *(const ulonglong2*)(wp + 256);
#pragma unroll 1
    for (int g = 0; g < 16; g++) {
        na = *(const ulonglong2*)(wp + 1 * WM_ROW_BYTES);
        nb = *(const ulonglong2*)(wp + 1 * WM_ROW_BYTES + 256);
        COMP1(qa, qb, xp);
        if (g < 15) {
            qa = *(const ulonglong2*)(wp + 2 * WM_ROW_BYTES);
            qb = *(const ulonglong2*)(wp + 2 * WM_ROW_BYTES + 256);
        }
        COMP1(na, nb, xp + 16);
        wp += 2 * WM_ROW_BYTES;
        xp += 32;
    }
#undef COMP1

    __syncthreads();  // xt done; reuse as reduction buffer (32KB exactly)

    // red planes: kind k in {c_lo, c_hi, mx_lo, mx_hi} x [b][j][hs][to]
#define RIDX(k, b, j, s, t) ((((((k) * 4 + (b)) * 2 + (j)) * 16 + (s)) * 16) + (t))
#pragma unroll
    for (int b = 0; b < 4; b++) {
#pragma unroll
        for (int j = 0; j < 2; j++) {
            float clo, chi;
            UNPACK2(clo, chi, c[b][j]);
            red[RIDX(0, b, j, hs, to)] = clo;
            red[RIDX(1, b, j, hs, to)] = chi;
            red[RIDX(2, b, j, hs, to)] = mxl[b][j];
            red[RIDX(3, b, j, hs, to)] = mxh[b][j];
        }
    }
    __syncthreads();

    // Final combine: 256 threads -> (b2 = tid>>6, o = tid&63).
    {
        const int b2 = tid >> 6;
        const int o = tid & 63;
        const int pr = o >> 1;       // local pair [0,32)
        const int h = o & 1;         // lo/hi half
        const int j2 = pr >> 4;
        const int to2 = pr & 15;
        float s = 0.f, M = -INFINITY;
#pragma unroll
        for (int g = 0; g < 16; g++) {
            s += red[RIDX(h, b2, j2, g, to2)];
            M = fmaxf(M, red[RIDX(2 + h, b2, j2, g, to2)]);
        }
        out[(b0 + b2) * OUTD + blockIdx.x * 64 + o] = s + DELTA_C * M;
    }
#undef RIDX
}

// ============================================================
extern "C" void kernel_launch(void* const* d_in, const int* in_sizes, int n_in,
                              void* d_out, int out_size) {
    const float* x  = (const float*)d_in[0];
    const float* w  = (const float*)d_in[1];
    const float* pe = (const float*)d_in[2];
    const float* aw = (const float*)d_in[3];
    const float* ab = (const float*)d_in[4];
    const float* lg = (const float*)d_in[5];
    const float* lb = (const float*)d_in[6];
    float* out = (float*)d_out;

    kernel_prep<<<512, 128>>>(w, aw, pe);
    kernel_scores<<<128, 128>>>(ab);
    kernel_lnwm<<<128, 128>>>(lg, lb);
    kernel_main<<<dim3(8, 64), 256>>>(x, out);
}

// round 12
// speedup vs baseline: 1.2545x; 1.2177x over previous
#include <cuda_runtime.h>
#include <math.h>

#define BB 256
#define IND 512
#define OUTD 512
#define ED 256
#define DELTA_C 0.1f
#define LN_EPS_C 1e-5f

typedef unsigned long long u64;

// Scratch (device globals — no allocation allowed)
__device__ float g_Wt[IND * OUTD];         // Wt[i][o] = W[o][i]
__device__ float g_scores[IND * OUTD];     // scores[i][o]
__device__ float4 g_WM[IND * (OUTD / 2)];  // (w_lo, w_hi, m_lo, m_hi)

// ---- packed f32x2 helpers (sm_100+; only add/mul/fma exist packed) ----
__device__ __forceinline__ u64 pack2(float lo, float hi) {
    u64 r; asm("mov.b64 %0, {%1,%2};" : "=l"(r) : "f"(lo), "f"(hi)); return r;
}
#define FMA2(d,a,b,c) asm("fma.rn.f32x2 %0,%1,%2,%3;" : "=l"(d) : "l"(a),"l"(b),"l"(c))
#define MUL2(d,a,b)   asm("mul.rn.f32x2 %0,%1,%2;"    : "=l"(d) : "l"(a),"l"(b))
#define UNPACK2(lo,hi,v) asm("mov.b64 {%0,%1}, %2;" : "=f"(lo),"=f"(hi) : "l"(v))

// ============================================================
// Kernel 1: W[o][i] -> g_Wt[i][o] only (AW/PE staging moved into scores).
// ============================================================
__global__ __launch_bounds__(128) void kernel_prep(const float* __restrict__ W) {
    __shared__ float tile[32][33];
    const int blk = blockIdx.x;
    const int tid = threadIdx.x;
    const int tx = tid & 31, ty = tid >> 5;

    int c = (blk & 15) * 32 + tx;
    int r0 = (blk >> 4) * 32;
#pragma unroll
    for (int j = 0; j < 32; j += 4)
        tile[ty + j][tx] = W[(r0 + ty + j) * IND + c];
    __syncthreads();
    int c2 = (blk >> 4) * 32 + tx;
    int r2 = (blk & 15) * 32;
#pragma unroll
    for (int j = 0; j < 32; j += 4)
        g_Wt[(r2 + ty + j) * OUTD + c2] = tile[tx][ty + j];
}

// ============================================================
// Kernel 2: tiled scores GEMM reading AW/PE DIRECTLY (transpose-on-stage).
// scores[i][o] = AB[o] + sum_e PE[i][e]*AW[o][e]
// grid 128 = (8 o-tiles of 64) x (16 i-tiles of 32), block 128.
// ============================================================
__global__ __launch_bounds__(128) void kernel_scores(
    const float* __restrict__ PE, const float* __restrict__ AW,
    const float* __restrict__ AB) {
    __shared__ float awb[2][32][68];   // [buf][e][o_local]
    __shared__ u64 peb[2][32][34];     // [buf][e][i_local] dup

    const int tid = threadIdx.x;
    const int to = tid & 15;
    const int ti = tid >> 4;
    const int o0 = (blockIdx.x & 7) * 64;
    const int i0 = (blockIdx.x >> 3) * 32;

    // AW staging map: 4 rows/warp, full 128B row segments
    const int a_ol = tid >> 3;          // [0,16): row group base (step 16)
    const int a_ec = (tid & 7) * 4;     // e column (floats)
    // PE staging map: 8 rows/warp
    const int p_il = tid >> 2;          // [0,32): i row
    const int p_ec = (tid & 3) * 8;     // e column base (floats)

    u64 acc[4][2];
    const u64 z = pack2(0.f, 0.f);
#pragma unroll
    for (int ii = 0; ii < 4; ii++) { acc[ii][0] = z; acc[ii][1] = z; }

    float4 qa[4];   // AW: rows a_ol + 16k
    float4 qp[2];   // PE: row p_il, e cols p_ec..p_ec+7

    auto LDGC = [&](int e0) {
#pragma unroll
        for (int k = 0; k < 4; k++)
            qa[k] = *(const float4*)(AW + (o0 + a_ol + 16 * k) * ED + e0 + a_ec);
#pragma unroll
        for (int k = 0; k < 2; k++)
            qp[k] = *(const float4*)(PE + (i0 + p_il) * ED + e0 + p_ec + 4 * k);
    };
    auto STSC = [&](int buf) {
#pragma unroll
        for (int k = 0; k < 4; k++) {
            awb[buf][a_ec + 0][a_ol + 16 * k] = qa[k].x;
            awb[buf][a_ec + 1][a_ol + 16 * k] = qa[k].y;
            awb[buf][a_ec + 2][a_ol + 16 * k] = qa[k].z;
            awb[buf][a_ec + 3][a_ol + 16 * k] = qa[k].w;
        }
#pragma unroll
        for (int k = 0; k < 2; k++) {
            peb[buf][p_ec + 4 * k + 0][p_il] = pack2(qp[k].x, qp[k].x);
            peb[buf][p_ec + 4 * k + 1][p_il] = pack2(qp[k].y, qp[k].y);
            peb[buf][p_ec + 4 * k + 2][p_il] = pack2(qp[k].z, qp[k].z);
            peb[buf][p_ec + 4 * k + 3][p_il] = pack2(qp[k].w, qp[k].w);
        }
    };
    auto COMPUTE = [&](int buf) {
#pragma unroll 4
        for (int e = 0; e < 32; e++) {
            ulonglong2 a = *(const ulonglong2*)&awb[buf][e][4 * to];
            ulonglong2 p01 = *(const ulonglong2*)&peb[buf][e][4 * ti];
            ulonglong2 p23 = *(const ulonglong2*)&peb[buf][e][4 * ti + 2];
            FMA2(acc[0][0], p01.x, a.x, acc[0][0]);
            FMA2(acc[0][1], p01.x, a.y, acc[0][1]);
            FMA2(acc[1][0], p01.y, a.x, acc[1][0]);
            FMA2(acc[1][1], p01.y, a.y, acc[1][1]);
            FMA2(acc[2][0], p23.x, a.x, acc[2][0]);
            FMA2(acc[2][1], p23.x, a.y, acc[2][1]);
            FMA2(acc[3][0], p23.y, a.x, acc[3][0]);
            FMA2(acc[3][1], p23.y, a.y, acc[3][1]);
        }
    };

    LDGC(0);
    STSC(0);
    __syncthreads();
#pragma unroll 1
    for (int c = 0; c < 8; c++) {
        if (c < 7) LDGC(32 * (c + 1));
        COMPUTE(c & 1);
        if (c < 7) {
            STSC((c + 1) & 1);
            __syncthreads();
        }
    }

    float4 bb = *(const float4*)(AB + o0 + 4 * to);
#pragma unroll
    for (int ii = 0; ii < 4; ii++) {
        float f0, f1, f2, f3;
        UNPACK2(f0, f1, acc[ii][0]);
        UNPACK2(f2, f3, acc[ii][1]);
        float4 o4;
        o4.x = f0 + bb.x; o4.y = f1 + bb.y;
        o4.z = f2 + bb.z; o4.w = f3 + bb.w;
        *(float4*)(g_scores + (i0 + 4 * ti + ii) * OUTD + o0 + 4 * to) = o4;
    }
}

// ============================================================
// Kernel 3: LayerNorm -> sigmoid -> interleaved g_WM float4 (unchanged)
// ============================================================
__global__ __launch_bounds__(128) void kernel_lnwm(
    const float* __restrict__ LG, const float* __restrict__ LB) {
    const int tid = threadIdx.x;
    const int i0 = blockIdx.x * 4;
    const int w = tid >> 5, lane = tid & 31;
    __shared__ float mus[4], rss[4];

    {
        const float* row = g_scores + (i0 + w) * OUTD;
        float s = 0.f, s2 = 0.f;
#pragma unroll
        for (int k = 0; k < 16; k++) {
            float v = row[lane + 32 * k];
            s += v; s2 += v * v;
        }
#pragma unroll
        for (int off = 16; off > 0; off >>= 1) {
            s  += __shfl_xor_sync(0xffffffffu, s,  off);
            s2 += __shfl_xor_sync(0xffffffffu, s2, off);
        }
        if (lane == 0) {
            float mu = s * (1.f / OUTD);
            float var = s2 * (1.f / OUTD) - mu * mu;
            mus[w] = mu;
            rss[w] = rsqrtf(var + LN_EPS_C);
        }
    }
    __syncthreads();
#pragma unroll
    for (int ii = 0; ii < 4; ii++) {
        float mu = mus[ii], rs = rss[ii];
        const int i = i0 + ii;
#pragma unroll
        for (int j = 0; j < 2; j++) {
            int p = tid + j * 128;
            float2 s2v = *(const float2*)(g_scores + i * OUTD + 2 * p);
            float2 w2v = *(const float2*)(g_Wt + i * OUTD + 2 * p);
            float glo = LG[2 * p],     blo = LB[2 * p];
            float ghi = LG[2 * p + 1], bhi = LB[2 * p + 1];
            float vlo = (s2v.x - mu) * rs * glo + blo;
            float vhi = (s2v.y - mu) * rs * ghi + bhi;
            float siglo = 1.f / (1.f + __expf(-vlo));
            float sighi = 1.f / (1.f + __expf(-vhi));
            float4 q;
            q.x = w2v.x; q.y = w2v.y;
            q.z = fabsf(w2v.x) * siglo;
            q.w = fabsf(w2v.y) * sighi;
            g_WM[i * (OUTD / 2) + p] = q;
        }
    }
}

// ============================================================
// Kernel 4 (main): out[b,o] = x@Wt + 0.1*(max_i t*M - sum_i t*M)
//
// B4 x P4: grid (4 o-tiles of 128, 64 b-tiles of 4) = 256 blocks,
// 256 thr, 2 blocks/SM (entire grid resident), 64KB dynamic smem.
// Thread (to=tid&15, hs=tid>>4): pairs {bx*64 + j*16 + to, j=0..3},
// i-chunk of 32. Per i: 4 LDS.128 (xt) + 4 LDG.128 (WM) feed 32
// outputs (0.25 ld/elem). Pointer-walk immediates, 1-i ping-pong.
// ============================================================
#define MAIN_SMEM (64 * 1024)
#define XT_B_BYTES 8192           // 512 i * 16 B
#define WM_ROW_BYTES 4096         // 256 pairs * 16 B

__global__ __launch_bounds__(256, 2) void kernel_main(
    const float* __restrict__ X, float* __restrict__ out) {
    extern __shared__ char smem_raw[];
    ulonglong2 (*xt)[IND] = (ulonglong2 (*)[IND])smem_raw;  // [4][512] = 32KB
    float* red = (float*)smem_raw;                          // 64KB after sync

    const int tid = threadIdx.x;
    const int to = tid & 15;
    const int hs = tid >> 4;        // [0,16), i-chunk of 32
    const int b0 = blockIdx.y * 4;
    const int ib = hs * 32;

    // Stage x and t = x*|x| duplicated for f32x2 broadcast (4 batches).
#pragma unroll
    for (int r = 0; r < 2; r++) {
        int idx = tid + r * 256;
        int b = idx >> 7, i4 = idx & 127;
        float4 xv = *(const float4*)(X + (b0 + b) * IND + i4 * 4);
        float xs[4] = {xv.x, xv.y, xv.z, xv.w};
#pragma unroll
        for (int k = 0; k < 4; k++) {
            float x1 = xs[k];
            float t1 = x1 * fabsf(x1);
            xt[b][i4 * 4 + k] = make_ulonglong2(pack2(x1, x1), pack2(t1, t1));
        }
    }
    __syncthreads();

    u64 c[4][4];                 // [b][j]  (16 u64 = 32 regs)
    float mxl[4][4], mxh[4][4];  // 32 regs
    const u64 z = pack2(0.f, 0.f);
    const u64 n01 = pack2(-DELTA_C, -DELTA_C);
#pragma unroll
    for (int b = 0; b < 4; b++)
#pragma unroll
        for (int j = 0; j < 4; j++) {
            c[b][j] = z;
            mxl[b][j] = -INFINITY;
            mxh[b][j] = -INFINITY;
        }

    // walking pointers
    const char* xp = smem_raw + ib * 16;
    const char* wp = (const char*)g_WM +
                     ((u64)ib * 256 + blockIdx.x * 64 + to) * 16;
    // pair j at wp + j*256

    ulonglong2 qa[4], na[4];

#define LOADG(q, base) do {                                          \
        (q)[0] = *(const ulonglong2*)((base));                       \
        (q)[1] = *(const ulonglong2*)((base) + 256);                 \
        (q)[2] = *(const ulonglong2*)((base) + 512);                 \
        (q)[3] = *(const ulonglong2*)((base) + 768);                 \
    } while (0)

#define COMPG(q, xb) do {                                            \
        _Pragma("unroll")                                            \
        for (int b = 0; b < 4; b++) {                                \
            ulonglong2 v = *(const ulonglong2*)((xb) + b * XT_B_BYTES); \
            _Pragma("unroll")                                        \
            for (int j = 0; j < 4; j++) {                            \
                FMA2(c[b][j], v.x, (q)[j].x, c[b][j]);               \
                u64 p; MUL2(p, v.y, (q)[j].y);                       \
                FMA2(c[b][j], p, n01, c[b][j]);                      \
                float plo, phi; UNPACK2(plo, phi, p);                \
                mxl[b][j] = fmaxf(mxl[b][j], plo);                   \
                mxh[b][j] = fmaxf(mxh[b][j], phi);                   \
            }                                                        \
        }                                                            \
    } while (0)

    LOADG(qa, wp);
#pragma unroll 1
    for (int g = 0; g < 16; g++) {
        LOADG(na, wp + 1 * WM_ROW_BYTES);
        COMPG(qa, xp);
        if (g < 15) LOADG(qa, wp + 2 * WM_ROW_BYTES);
        COMPG(na, xp + 16);
        wp += 2 * WM_ROW_BYTES;
        xp += 32;
    }
#undef LOADG
#undef COMPG

    __syncthreads();  // xt done; reuse full 64KB as reduction buffer

    // red planes: [k 4][b 4][j 4][hs 16][to 16] = 16384 floats = 64KB
#define RIDX(k, b, j, s, t) ((((((k) * 4 + (b)) * 4 + (j)) * 16 + (s)) * 16) + (t))
#pragma unroll
    for (int b = 0; b < 4; b++)
#pragma unroll
        for (int j = 0; j < 4; j++) {
            float clo, chi;
            UNPACK2(clo, chi, c[b][j]);
            red[RIDX(0, b, j, hs, to)] = clo;
            red[RIDX(1, b, j, hs, to)] = chi;
            red[RIDX(2, b, j, hs, to)] = mxl[b][j];
            red[RIDX(3, b, j, hs, to)] = mxh[b][j];
        }
    __syncthreads();

    // Final combine: 256 threads -> (b2 = tid>>6, pl = tid&63 pair).
    {
        const int b2 = tid >> 6;
        const int pl = tid & 63;
        const int j2 = pl >> 4;
        const int to2 = pl & 15;
        float slo = 0.f, shi = 0.f, Mlo = -INFINITY, Mhi = -INFINITY;
#pragma unroll
        for (int s = 0; s < 16; s++) {
            slo += red[RIDX(0, b2, j2, s, to2)];
            shi += red[RIDX(1, b2, j2, s, to2)];
            Mlo = fmaxf(Mlo, red[RIDX(2, b2, j2, s, to2)]);
            Mhi = fmaxf(Mhi, red[RIDX(3, b2, j2, s, to2)]);
        }
        float2 r;
        r.x = slo + DELTA_C * Mlo;
        r.y = shi + DELTA_C * Mhi;
        *(float2*)(out + (b0 + b2) * OUTD + blockIdx.x * 128 + j2 * 32 + to2 * 2) = r;
    }
#undef RIDX
}

// ============================================================
extern "C" void kernel_launch(void* const* d_in, const int* in_sizes, int n_in,
                              void* d_out, int out_size) {
    const float* x  = (const float*)d_in[0];
    const float* w  = (const float*)d_in[1];
    const float* pe = (const float*)d_in[2];
    const float* aw = (const float*)d_in[3];
    const float* ab = (const float*)d_in[4];
    const float* lg = (const float*)d_in[5];
    const float* lb = (const float*)d_in[6];
    float* out = (float*)d_out;

    cudaFuncSetAttribute(kernel_main,
                         cudaFuncAttributeMaxDynamicSharedMemorySize,
                         MAIN_SMEM);

    kernel_prep<<<256, 128>>>(w);
    kernel_scores<<<128, 128>>>(pe, aw, ab);
    kernel_lnwm<<<128, 128>>>(lg, lb);
    kernel_main<<<dim3(4, 64), 256, MAIN_SMEM>>>(x, out);
}

// round 13
// speedup vs baseline: 1.2590x; 1.0036x over previous
#include <cuda_runtime.h>
#include <math.h>

#define BB 256
#define IND 512
#define OUTD 512
#define ED 256
#define DELTA_C 0.1f
#define LN_EPS_C 1e-5f

typedef unsigned long long u64;

// Scratch (device globals — no allocation allowed)
__device__ float g_Wt[IND * OUTD];         // Wt[i][o] = W[o][i]
__device__ float g_AWt[ED * OUTD];         // AWt[e][o] = attn_w[o][e]
__device__ u64 g_PE2[ED * IND];            // PE2[e][i] = (PE[i][e], PE[i][e])
__device__ float g_scores[IND * OUTD];     // scores[i][o]
__device__ float4 g_WM[IND * (OUTD / 2)];  // (w_lo, w_hi, m_lo, m_hi)

// ---- packed f32x2 helpers (sm_100+; only add/mul/fma exist packed) ----
__device__ __forceinline__ u64 pack2(float lo, float hi) {
    u64 r; asm("mov.b64 %0, {%1,%2};" : "=l"(r) : "f"(lo), "f"(hi)); return r;
}
#define FMA2(d,a,b,c) asm("fma.rn.f32x2 %0,%1,%2,%3;" : "=l"(d) : "l"(a),"l"(b),"l"(c))
#define MUL2(d,a,b)   asm("mul.rn.f32x2 %0,%1,%2;"    : "=l"(d) : "l"(a),"l"(b))
#define UNPACK2(lo,hi,v) asm("mov.b64 {%0,%1}, %2;" : "=f"(lo),"=f"(hi) : "l"(v))

// ============================================================
// Kernel 1: transposes / relayouts (R7/R11 known-good).
//   blocks [0,256):   W[o][i]  -> g_Wt[i][o]
//   blocks [256,384): AW[o][e] -> g_AWt[e][o]
//   blocks [384,512): PE[i][e] -> g_PE2[e][i] (duplicated u64)
// ============================================================
__global__ __launch_bounds__(128) void kernel_prep(
    const float* __restrict__ W, const float* __restrict__ AW,
    const float* __restrict__ PE) {
    __shared__ float tile[32][33];
    const int blk = blockIdx.x;
    const int tid = threadIdx.x;
    const int tx = tid & 31, ty = tid >> 5;

    if (blk < 256) {
        int c = (blk & 15) * 32 + tx;
        int r0 = (blk >> 4) * 32;
#pragma unroll
        for (int j = 0; j < 32; j += 4)
            tile[ty + j][tx] = W[(r0 + ty + j) * IND + c];
        __syncthreads();
        int c2 = (blk >> 4) * 32 + tx;
        int r2 = (blk & 15) * 32;
#pragma unroll
        for (int j = 0; j < 32; j += 4)
            g_Wt[(r2 + ty + j) * OUTD + c2] = tile[tx][ty + j];
    } else if (blk < 384) {
        int t = blk - 256;
        int o0 = (t & 15) * 32;
        int e0 = (t >> 4) * 32;
#pragma unroll
        for (int j = 0; j < 32; j += 4)
            tile[ty + j][tx] = AW[(o0 + ty + j) * ED + e0 + tx];
        __syncthreads();
#pragma unroll
        for (int j = 0; j < 32; j += 4)
            g_AWt[(e0 + ty + j) * OUTD + o0 + tx] = tile[tx][ty + j];
    } else {
        int t = blk - 384;
        int i0 = (t & 15) * 32;
        int e0 = (t >> 4) * 32;
#pragma unroll
        for (int j = 0; j < 32; j += 4)
            tile[ty + j][tx] = PE[(i0 + ty + j) * ED + e0 + tx];
        __syncthreads();
#pragma unroll
        for (int j = 0; j < 32; j += 4) {
            float v = tile[tx][ty + j];
            g_PE2[(e0 + ty + j) * IND + i0 + tx] = pack2(v, v);
        }
    }
}

// ============================================================
// Kernel 2: tiled scores GEMM from g_AWt/g_PE2 (R7/R11 known-good).
// scores[i][o] = AB[o] + sum_e PE[i][e]*AWt[e][o]
// grid 128 = (8 o-tiles of 64) x (16 i-tiles of 32), block 128.
// ============================================================
__global__ __launch_bounds__(128) void kernel_scores(
    const float* __restrict__ AB) {
    __shared__ float awb[2][32][68];
    __shared__ u64 peb[2][32][34];

    const int tid = threadIdx.x;
    const int to = tid & 15;
    const int ti = tid >> 4;
    const int o0 = (blockIdx.x & 7) * 64;
    const int i0 = (blockIdx.x >> 3) * 32;

    const int sr = tid >> 4;
    const int sc = tid & 15;

    u64 acc[4][2];
    const u64 z = pack2(0.f, 0.f);
#pragma unroll
    for (int ii = 0; ii < 4; ii++) { acc[ii][0] = z; acc[ii][1] = z; }

    float4 qa[4];
    ulonglong2 qp[4];

    auto LDGC = [&](int e0) {
#pragma unroll
        for (int k = 0; k < 4; k++) {
            int row = sr + k * 8;
            qa[k] = *(const float4*)(g_AWt + (e0 + row) * OUTD + o0 + sc * 4);
            qp[k] = *(const ulonglong2*)(g_PE2 + (e0 + row) * IND + i0 + sc * 2);
        }
    };
    auto STSC = [&](int buf) {
#pragma unroll
        for (int k = 0; k < 4; k++) {
            int row = sr + k * 8;
            *(float4*)&awb[buf][row][sc * 4] = qa[k];
            *(ulonglong2*)&peb[buf][row][sc * 2] = qp[k];
        }
    };
    auto COMPUTE = [&](int buf) {
#pragma unroll 4
        for (int e = 0; e < 32; e++) {
            ulonglong2 a = *(const ulonglong2*)&awb[buf][e][4 * to];
            ulonglong2 p01 = *(const ulonglong2*)&peb[buf][e][4 * ti];
            ulonglong2 p23 = *(const ulonglong2*)&peb[buf][e][4 * ti + 2];
            FMA2(acc[0][0], p01.x, a.x, acc[0][0]);
            FMA2(acc[0][1], p01.x, a.y, acc[0][1]);
            FMA2(acc[1][0], p01.y, a.x, acc[1][0]);
            FMA2(acc[1][1], p01.y, a.y, acc[1][1]);
            FMA2(acc[2][0], p23.x, a.x, acc[2][0]);
            FMA2(acc[2][1], p23.x, a.y, acc[2][1]);
            FMA2(acc[3][0], p23.y, a.x, acc[3][0]);
            FMA2(acc[3][1], p23.y, a.y, acc[3][1]);
        }
    };

    LDGC(0);
    STSC(0);
    __syncthreads();
#pragma unroll 1
    for (int c = 0; c < 8; c++) {
        if (c < 7) LDGC(32 * (c + 1));
        COMPUTE(c & 1);
        if (c < 7) {
            STSC((c + 1) & 1);
            __syncthreads();
        }
    }

    float4 bb = *(const float4*)(AB + o0 + 4 * to);
#pragma unroll
    for (int ii = 0; ii < 4; ii++) {
        float f0, f1, f2, f3;
        UNPACK2(f0, f1, acc[ii][0]);
        UNPACK2(f2, f3, acc[ii][1]);
        float4 o4;
        o4.x = f0 + bb.x; o4.y = f1 + bb.y;
        o4.z = f2 + bb.z; o4.w = f3 + bb.w;
        *(float4*)(g_scores + (i0 + 4 * ti + ii) * OUTD + o0 + 4 * to) = o4;
    }
}

// ============================================================
// Kernel 3: LayerNorm -> sigmoid -> interleaved g_WM float4 (unchanged)
// ============================================================
__global__ __launch_bounds__(128) void kernel_lnwm(
    const float* __restrict__ LG, const float* __restrict__ LB) {
    const int tid = threadIdx.x;
    const int i0 = blockIdx.x * 4;
    const int w = tid >> 5, lane = tid & 31;
    __shared__ float mus[4], rss[4];

    {
        const float* row = g_scores + (i0 + w) * OUTD;
        float s = 0.f, s2 = 0.f;
#pragma unroll
        for (int k = 0; k < 16; k++) {
            float v = row[lane + 32 * k];
            s += v; s2 += v * v;
        }
#pragma unroll
        for (int off = 16; off > 0; off >>= 1) {
            s  += __shfl_xor_sync(0xffffffffu, s,  off);
            s2 += __shfl_xor_sync(0xffffffffu, s2, off);
        }
        if (lane == 0) {
            float mu = s * (1.f / OUTD);
            float var = s2 * (1.f / OUTD) - mu * mu;
            mus[w] = mu;
            rss[w] = rsqrtf(var + LN_EPS_C);
        }
    }
    __syncthreads();
#pragma unroll
    for (int ii = 0; ii < 4; ii++) {
        float mu = mus[ii], rs = rss[ii];
        const int i = i0 + ii;
#pragma unroll
        for (int j = 0; j < 2; j++) {
            int p = tid + j * 128;
            float2 s2v = *(const float2*)(g_scores + i * OUTD + 2 * p);
            float2 w2v = *(const float2*)(g_Wt + i * OUTD + 2 * p);
            float glo = LG[2 * p],     blo = LB[2 * p];
            float ghi = LG[2 * p + 1], bhi = LB[2 * p + 1];
            float vlo = (s2v.x - mu) * rs * glo + blo;
            float vhi = (s2v.y - mu) * rs * ghi + bhi;
            float siglo = 1.f / (1.f + __expf(-vlo));
            float sighi = 1.f / (1.f + __expf(-vhi));
            float4 q;
            q.x = w2v.x; q.y = w2v.y;
            q.z = fabsf(w2v.x) * siglo;
            q.w = fabsf(w2v.y) * sighi;
            g_WM[i * (OUTD / 2) + p] = q;
        }
    }
}

// ============================================================
// Kernel 4 (main): out[b,o] = x@Wt + 0.1*(max_i t*M - sum_i t*M)
// (FROZEN from R12 — measured 21.7us)
// B4 x P4: grid (4 o-tiles of 128, 64 b-tiles of 4) = 256 blocks,
// 256 thr, 2 blocks/SM, 64KB dynamic smem. 0.25 ld/elem.
// ============================================================
#define MAIN_SMEM (64 * 1024)
#define XT_B_BYTES 8192           // 512 i * 16 B
#define WM_ROW_BYTES 4096         // 256 pairs * 16 B

__global__ __launch_bounds__(256, 2) void kernel_main(
    const float* __restrict__ X, float* __restrict__ out) {
    extern __shared__ char smem_raw[];
    ulonglong2 (*xt)[IND] = (ulonglong2 (*)[IND])smem_raw;  // [4][512] = 32KB
    float* red = (float*)smem_raw;                          // 64KB after sync

    const int tid = threadIdx.x;
    const int to = tid & 15;
    const int hs = tid >> 4;        // [0,16), i-chunk of 32
    const int b0 = blockIdx.y * 4;
    const int ib = hs * 32;

    // Stage x and t = x*|x| duplicated for f32x2 broadcast (4 batches).
#pragma unroll
    for (int r = 0; r < 2; r++) {
        int idx = tid + r * 256;
        int b = idx >> 7, i4 = idx & 127;
        float4 xv = *(const float4*)(X + (b0 + b) * IND + i4 * 4);
        float xs[4] = {xv.x, xv.y, xv.z, xv.w};
#pragma unroll
        for (int k = 0; k < 4; k++) {
            float x1 = xs[k];
            float t1 = x1 * fabsf(x1);
            xt[b][i4 * 4 + k] = make_ulonglong2(pack2(x1, x1), pack2(t1, t1));
        }
    }
    __syncthreads();

    u64 c[4][4];
    float mxl[4][4], mxh[4][4];
    const u64 z = pack2(0.f, 0.f);
    const u64 n01 = pack2(-DELTA_C, -DELTA_C);
#pragma unroll
    for (int b = 0; b < 4; b++)
#pragma unroll
        for (int j = 0; j < 4; j++) {
            c[b][j] = z;
            mxl[b][j] = -INFINITY;
            mxh[b][j] = -INFINITY;
        }

    const char* xp = smem_raw + ib * 16;
    const char* wp = (const char*)g_WM +
                     ((u64)ib * 256 + blockIdx.x * 64 + to) * 16;

    ulonglong2 qa[4], na[4];

#define LOADG(q, base) do {                                          \
        (q)[0] = *(const ulonglong2*)((base));                       \
        (q)[1] = *(const ulonglong2*)((base) + 256);                 \
        (q)[2] = *(const ulonglong2*)((base) + 512);                 \
        (q)[3] = *(const ulonglong2*)((base) + 768);                 \
    } while (0)

#define COMPG(q, xb) do {                                            \
        _Pragma("unroll")                                            \
        for (int b = 0; b < 4; b++) {                                \
            ulonglong2 v = *(const ulonglong2*)((xb) + b * XT_B_BYTES); \
            _Pragma("unroll")                                        \
            for (int j = 0; j < 4; j++) {                            \
                FMA2(c[b][j], v.x, (q)[j].x, c[b][j]);               \
                u64 p; MUL2(p, v.y, (q)[j].y);                       \
                FMA2(c[b][j], p, n01, c[b][j]);                      \
                float plo, phi; UNPACK2(plo, phi, p);                \
                mxl[b][j] = fmaxf(mxl[b][j], plo);                   \
                mxh[b][j] = fmaxf(mxh[b][j], phi);                   \
            }                                                        \
        }                                                            \
    } while (0)

    LOADG(qa, wp);
#pragma unroll 1
    for (int g = 0; g < 16; g++) {
        LOADG(na, wp + 1 * WM_ROW_BYTES);
        COMPG(qa, xp);
        if (g < 15) LOADG(qa, wp + 2 * WM_ROW_BYTES);
        COMPG(na, xp + 16);
        wp += 2 * WM_ROW_BYTES;
        xp += 32;
    }
#undef LOADG
#undef COMPG

    __syncthreads();

#define RIDX(k, b, j, s, t) ((((((k) * 4 + (b)) * 4 + (j)) * 16 + (s)) * 16) + (t))
#pragma unroll
    for (int b = 0; b < 4; b++)
#pragma unroll
        for (int j = 0; j < 4; j++) {
            float clo, chi;
            UNPACK2(clo, chi, c[b][j]);
            red[RIDX(0, b, j, hs, to)] = clo;
            red[RIDX(1, b, j, hs, to)] = chi;
            red[RIDX(2, b, j, hs, to)] = mxl[b][j];
            red[RIDX(3, b, j, hs, to)] = mxh[b][j];
        }
    __syncthreads();

    {
        const int b2 = tid >> 6;
        const int pl = tid & 63;
        const int j2 = pl >> 4;
        const int to2 = pl & 15;
        float slo = 0.f, shi = 0.f, Mlo = -INFINITY, Mhi = -INFINITY;
#pragma unroll
        for (int s = 0; s < 16; s++) {
            slo += red[RIDX(0, b2, j2, s, to2)];
            shi += red[RIDX(1, b2, j2, s, to2)];
            Mlo = fmaxf(Mlo, red[RIDX(2, b2, j2, s, to2)]);
            Mhi = fmaxf(Mhi, red[RIDX(3, b2, j2, s, to2)]);
        }
        float2 r;
        r.x = slo + DELTA_C * Mlo;
        r.y = shi + DELTA_C * Mhi;
        *(float2*)(out + (b0 + b2) * OUTD + blockIdx.x * 128 + j2 * 32 + to2 * 2) = r;
    }
#undef RIDX
}

// ============================================================
extern "C" void kernel_launch(void* const* d_in, const int* in_sizes, int n_in,
                              void* d_out, int out_size) {
    const float* x  = (const float*)d_in[0];
    const float* w  = (const float*)d_in[1];
    const float* pe = (const float*)d_in[2];
    const float* aw = (const float*)d_in[3];
    const float* ab = (const float*)d_in[4];
    const float* lg = (const float*)d_in[5];
    const float* lb = (const float*)d_in[6];
    float* out = (float*)d_out;

    cudaFuncSetAttribute(kernel_main,
                         cudaFuncAttributeMaxDynamicSharedMemorySize,
                         MAIN_SMEM);

    kernel_prep<<<512, 128>>>(w, aw, pe);
    kernel_scores<<<128, 128>>>(ab);
    kernel_lnwm<<<128, 128>>>(lg, lb);
    kernel_main<<<dim3(4, 64), 256, MAIN_SMEM>>>(x, out);
}